// round 1
// baseline (speedup 1.0000x reference)
#include <cuda_runtime.h>

// Operator3D: bs=4, v=8192, n=20, SUPPORT=4, KERNEL=32  (S*K = 128)
// inputs: [0] neighbor_index int32 (bs,v,n)
//         [1] vertices       f32   (bs,v,3)
//         [2] weights        f32   (1,1,4,32)
//         [3] displacement   f32   (3,128)
// output: feature f32 (bs,v,32)

#define BS_   4
#define V_    8192
#define N_    20
#define K_    32
#define SK_   128
#define ROWS_ (BS_ * V_)

#define WARPS_PER_BLOCK 8
#define THREADS_ (WARPS_PER_BLOCK * 32)

__global__ __launch_bounds__(THREADS_)
void op3d_kernel(const int*   __restrict__ nb,
                 const float* __restrict__ verts,
                 const float* __restrict__ weights,
                 const float* __restrict__ disp,
                 float*       __restrict__ out,
                 int nwarps)
{
    __shared__ float4 sdisp[WARPS_PER_BLOCK][N_];

    const int warp  = threadIdx.x >> 5;
    const int lane  = threadIdx.x & 31;
    const int gwarp = blockIdx.x * WARPS_PER_BLOCK + warp;

    // Per-lane constants: displacement columns for k = s*32 + lane, s=0..3,
    // rows d=0..2 of the (3,128) displacement matrix; plus weights.
    const float d00 = disp[0 * SK_ +  0 + lane];
    const float d01 = disp[0 * SK_ + 32 + lane];
    const float d02 = disp[0 * SK_ + 64 + lane];
    const float d03 = disp[0 * SK_ + 96 + lane];
    const float d10 = disp[1 * SK_ +  0 + lane];
    const float d11 = disp[1 * SK_ + 32 + lane];
    const float d12 = disp[1 * SK_ + 64 + lane];
    const float d13 = disp[1 * SK_ + 96 + lane];
    const float d20 = disp[2 * SK_ +  0 + lane];
    const float d21 = disp[2 * SK_ + 32 + lane];
    const float d22 = disp[2 * SK_ + 64 + lane];
    const float d23 = disp[2 * SK_ + 96 + lane];
    const float w0  = weights[ 0 + lane];
    const float w1  = weights[32 + lane];
    const float w2  = weights[64 + lane];
    const float w3  = weights[96 + lane];

    for (int r = gwarp; r < ROWS_; r += nwarps) {
        const int b     = r >> 13;            // r / V_  (V_ = 8192)
        const int vbase = b * (V_ * 3);

        if (lane < N_) {
            const int idx = nb[r * N_ + lane];
            const float* p = verts + vbase + idx * 3;
            const float* q = verts + r * 3;
            float dx = p[0] - q[0];
            float dy = p[1] - q[1];
            float dz = p[2] - q[2];
            sdisp[warp][lane] = make_float4(dx, dy, dz, 0.0f);
        }
        __syncwarp();

        // running max initialized to 0 == relu(max_n theta) since relu is monotone
        float m0 = 0.0f, m1 = 0.0f, m2 = 0.0f, m3 = 0.0f;
        #pragma unroll
        for (int j = 0; j < N_; j++) {
            const float4 d = sdisp[warp][j];
            float t0 = fmaf(d.x, d00, fmaf(d.y, d10, d.z * d20));
            float t1 = fmaf(d.x, d01, fmaf(d.y, d11, d.z * d21));
            float t2 = fmaf(d.x, d02, fmaf(d.y, d12, d.z * d22));
            float t3 = fmaf(d.x, d03, fmaf(d.y, d13, d.z * d23));
            m0 = fmaxf(m0, t0);
            m1 = fmaxf(m1, t1);
            m2 = fmaxf(m2, t2);
            m3 = fmaxf(m3, t3);
        }

        out[r * K_ + lane] = fmaf(m0, w0, fmaf(m1, w1, fmaf(m2, w2, m3 * w3)));
        __syncwarp();   // protect smem before next iteration's writes
    }
}

extern "C" void kernel_launch(void* const* d_in, const int* in_sizes, int n_in,
                              void* d_out, int out_size)
{
    const int*   nb      = (const int*)  d_in[0];
    const float* verts   = (const float*)d_in[1];
    const float* weights = (const float*)d_in[2];
    const float* disp    = (const float*)d_in[3];
    float*       out     = (float*)      d_out;

    const int blocks = 512;                         // 4096 warps -> 8 rows/warp
    const int nwarps = blocks * WARPS_PER_BLOCK;
    op3d_kernel<<<blocks, THREADS_>>>(nb, verts, weights, disp, out, nwarps);
}

// round 2
// speedup vs baseline: 1.0960x; 1.0960x over previous
#include <cuda_runtime.h>

// Operator3D: bs=4, v=8192, n=20, SUPPORT=4, KERNEL=32  (S*K = 128)
// inputs: [0] neighbor_index int32 (bs,v,n)
//         [1] vertices       f32   (bs,v,3)
//         [2] weights        f32   (1,1,4,32)
//         [3] displacement   f32   (3,128)
// output: feature f32 (bs,v,32)

#define BS_   4
#define V_    8192
#define N_    20
#define K_    32
#define SK_   128
#define ROWS_ (BS_ * V_)

#define WARPS_PER_BLOCK 8
#define THREADS_ (WARPS_PER_BLOCK * 32)

typedef unsigned long long u64;

__device__ __forceinline__ u64 packf2(float lo, float hi) {
    u64 r;
    asm("mov.b64 %0, {%1, %2};" : "=l"(r) : "f"(lo), "f"(hi));
    return r;
}
__device__ __forceinline__ void unpackf2(float& lo, float& hi, u64 v) {
    asm("mov.b64 {%0, %1}, %2;" : "=f"(lo), "=f"(hi) : "l"(v));
}
#define FMA_F32X2(out, a, b, c) \
    asm("fma.rn.f32x2 %0, %1, %2, %3;" : "=l"(out) : "l"(a), "l"(b), "l"(c))
#define MUL_F32X2_(out, a, b) \
    asm("mul.rn.f32x2 %0, %1, %2;" : "=l"(out) : "l"(a), "l"(b))

// per-neighbor staged displacement, duplicated into f32x2 lanes
struct alignas(16) Pair3 {
    u64 x2;   // (dx, dx)
    u64 y2;   // (dy, dy)
    u64 z2;   // (dz, dz)
    u64 pad;
};

__global__ __launch_bounds__(THREADS_)
void op3d_kernel(const int*   __restrict__ nb,
                 const float* __restrict__ verts,
                 const float* __restrict__ weights,
                 const float* __restrict__ disp,
                 float*       __restrict__ out)
{
    __shared__ Pair3 sdisp[WARPS_PER_BLOCK][N_];

    const int warp = threadIdx.x >> 5;
    const int lane = threadIdx.x & 31;
    const int r    = blockIdx.x * WARPS_PER_BLOCK + warp;   // one row per warp
    if (r >= ROWS_) return;

    // Packed per-lane displacement-matrix columns:
    // component0 = support s (k = s*32+lane) pairs (s0,s1) and (s2,s3)
    const u64 D0_01 = packf2(disp[0*SK_ +  0 + lane], disp[0*SK_ + 32 + lane]);
    const u64 D0_23 = packf2(disp[0*SK_ + 64 + lane], disp[0*SK_ + 96 + lane]);
    const u64 D1_01 = packf2(disp[1*SK_ +  0 + lane], disp[1*SK_ + 32 + lane]);
    const u64 D1_23 = packf2(disp[1*SK_ + 64 + lane], disp[1*SK_ + 96 + lane]);
    const u64 D2_01 = packf2(disp[2*SK_ +  0 + lane], disp[2*SK_ + 32 + lane]);
    const u64 D2_23 = packf2(disp[2*SK_ + 64 + lane], disp[2*SK_ + 96 + lane]);
    const float w0 = weights[ 0 + lane];
    const float w1 = weights[32 + lane];
    const float w2 = weights[64 + lane];
    const float w3 = weights[96 + lane];

    const int b     = r >> 13;                 // r / V_
    const int vbase = b * (V_ * 3);

    if (lane < N_) {
        const int idx  = nb[r * N_ + lane];
        const float* p = verts + vbase + idx * 3;
        const float* q = verts + r * 3;
        float dx = p[0] - q[0];
        float dy = p[1] - q[1];
        float dz = p[2] - q[2];
        Pair3 pr;
        pr.x2 = packf2(dx, dx);
        pr.y2 = packf2(dy, dy);
        pr.z2 = packf2(dz, dz);
        sdisp[warp][lane] = pr;
    }
    __syncwarp();

    // relu(max_n theta): running max seeded at 0 implements the relu for free
    float m0 = 0.0f, m1 = 0.0f, m2 = 0.0f, m3 = 0.0f;
    #pragma unroll
    for (int j = 0; j < N_; j++) {
        const u64 dx2 = sdisp[warp][j].x2;
        const u64 dy2 = sdisp[warp][j].y2;
        const u64 dz2 = sdisp[warp][j].z2;

        u64 t01, t23, a01, a23;
        MUL_F32X2_(a01, dz2, D2_01);
        FMA_F32X2(t01, dy2, D1_01, a01);
        FMA_F32X2(t01, dx2, D0_01, t01);
        MUL_F32X2_(a23, dz2, D2_23);
        FMA_F32X2(t23, dy2, D1_23, a23);
        FMA_F32X2(t23, dx2, D0_23, t23);

        float t0, t1, t2, t3;
        unpackf2(t0, t1, t01);
        unpackf2(t2, t3, t23);
        m0 = fmaxf(m0, t0);
        m1 = fmaxf(m1, t1);
        m2 = fmaxf(m2, t2);
        m3 = fmaxf(m3, t3);
    }

    out[r * K_ + lane] = fmaf(m0, w0, fmaf(m1, w1, fmaf(m2, w2, m3 * w3)));
}

extern "C" void kernel_launch(void* const* d_in, const int* in_sizes, int n_in,
                              void* d_out, int out_size)
{
    const int*   nb      = (const int*)  d_in[0];
    const float* verts   = (const float*)d_in[1];
    const float* weights = (const float*)d_in[2];
    const float* disp    = (const float*)d_in[3];
    float*       out     = (float*)      d_out;

    const int blocks = ROWS_ / WARPS_PER_BLOCK;   // 4096: one row per warp
    op3d_kernel<<<blocks, THREADS_>>>(nb, verts, weights, disp, out);
}